// round 8
// baseline (speedup 1.0000x reference)
#include <cuda_runtime.h>
#include <cstdint>

#define Bn 64
#define Sn 128
#define Dn 512
#define Tn 64
#define N3 1536      // 3*D
#define GK 515       // D + 3
#define GKP 528      // padded to multiple of 16

// ---------------- scratch (device globals; no allocation) ----------------
__device__ float g_Uk[Bn * Sn * Dn];        // [B,S,D] keys projection
__device__ float g_h[Bn * Dn];              // hidden state (in-place update)
__device__ float g_qpart[8][Bn * Dn];       // split-K partials of q
__device__ float g_gipart[4][Bn * N3];      // split-K partials of gi
__device__ float g_ghpart[4][Bn * N3];      // split-K partials of gh
__device__ float g_gin[Bn * GKP];           // [ctx | x | zero-pad]
__device__ float g_Wpad[N3 * GKP];          // W_ih zero-padded to K=528

__device__ __forceinline__ float tanh_fast(float x) {
    float y; asm("tanh.approx.f32 %0, %1;" : "=f"(y) : "f"(x)); return y;
}

__device__ __forceinline__ float gru_one(float gir, float ghr, float giz, float ghz,
                                         float gnn, float ghn, float h) {
    float r = 1.f / (1.f + __expf(-(gir + ghr)));
    float z = 1.f / (1.f + __expf(-(giz + ghz)));
    float n = tanhf(gnn + r * ghn);
    return (1.f - z) * n + z * h;
}

__device__ __forceinline__ void add4(float4& a, const float* p) {
    float4 v = *(const float4*)p;
    a.x += v.x; a.y += v.y; a.z += v.z; a.w += v.w;
}

struct SmemGemm { float As[16][68]; float Bs[16][68]; };

// C[64 x 64] tile of  C = A(MxK) * B  (+bias), BK=16, 256 threads, 4x4 microtile.
// NT=false: B row-major [K,N];  NT=true: B row-major [N,K].
template <bool NT>
__device__ __forceinline__ void gemm64(const float* __restrict__ A, int lda,
                                       const float* __restrict__ B, int ldb,
                                       float* __restrict__ C, int ldc,
                                       const float* __restrict__ bias,
                                       int m0, int n0, int k0, int kiters,
                                       SmemGemm& s)
{
    const int tid = threadIdx.x;
    const int tx = tid & 15, ty = tid >> 4;
    const int am = tid >> 2, ak = (tid & 3) << 2;
    float acc[4][4] = {};

    for (int it = 0; it < kiters; ++it) {
        const int k = k0 + it * 16;
        float4 a4 = *(const float4*)&A[(size_t)(m0 + am) * lda + k + ak];
        float4 b4;
        if (NT) {
            b4 = *(const float4*)&B[(size_t)(n0 + am) * ldb + k + ak];
        } else {
            const int bk = tid >> 4, bn = (tid & 15) << 2;
            b4 = *(const float4*)&B[(size_t)(k + bk) * ldb + n0 + bn];
        }
        __syncthreads();
        s.As[ak + 0][am] = a4.x; s.As[ak + 1][am] = a4.y;
        s.As[ak + 2][am] = a4.z; s.As[ak + 3][am] = a4.w;
        if (NT) {
            s.Bs[ak + 0][am] = b4.x; s.Bs[ak + 1][am] = b4.y;
            s.Bs[ak + 2][am] = b4.z; s.Bs[ak + 3][am] = b4.w;
        } else {
            const int bk = tid >> 4, bn = (tid & 15) << 2;
            *(float4*)&s.Bs[bk][bn] = b4;
        }
        __syncthreads();
        #pragma unroll
        for (int kk = 0; kk < 16; ++kk) {
            float4 av = *(const float4*)&s.As[kk][ty << 2];
            float4 bv = *(const float4*)&s.Bs[kk][tx << 2];
            float a[4] = {av.x, av.y, av.z, av.w};
            float b[4] = {bv.x, bv.y, bv.z, bv.w};
            #pragma unroll
            for (int u = 0; u < 4; ++u)
                #pragma unroll
                for (int v = 0; v < 4; ++v)
                    acc[u][v] += a[u] * b[v];
        }
    }

    float4 bi = make_float4(0.f, 0.f, 0.f, 0.f);
    if (bias) bi = *(const float4*)&bias[n0 + (tx << 2)];
    #pragma unroll
    for (int u = 0; u < 4; ++u) {
        float4 o;
        o.x = acc[u][0] + bi.x; o.y = acc[u][1] + bi.y;
        o.z = acc[u][2] + bi.z; o.w = acc[u][3] + bi.w;
        *(float4*)&C[(size_t)(m0 + (ty << 2) + u) * ldc + n0 + (tx << 2)] = o;
    }
}

// ---------------- kernels ----------------

__global__ void k_init(const float* __restrict__ e_last,
                       const float* __restrict__ W_ih)
{
    const int i = blockIdx.x * blockDim.x + threadIdx.x;
    const int stride = gridDim.x * blockDim.x;
    if (i < Bn * Dn) g_h[i] = e_last[i];
    if (i < Bn * 16) {                     // zero x + pad region of gin
        int b = i >> 4, k = i & 15;
        g_gin[b * GKP + Dn + k] = 0.f;
    }
    for (int j = i; j < N3 * GKP; j += stride) {
        int n = j / GKP, k = j - n * GKP;
        g_Wpad[j] = (k < GK) ? W_ih[n * GK + k] : 0.f;
    }
}

// Uk = e_all @ Ua_w + Ua_b    (M = B*S = 8192, N = K = 512)
__global__ void k_uk(const float* __restrict__ e_all,
                     const float* __restrict__ Ua_w,
                     const float* __restrict__ Ua_b)
{
    __shared__ SmemGemm s;
    gemm64<false>(e_all, Dn, Ua_w, Dn, g_Uk, Dn, Ua_b,
                  blockIdx.y * 64, blockIdx.x * 64, 0, 32, s);
}

// GRU gates: h(in)+parts -> h(out), PLUS out = h_new @ Wo + b (written to
// d_outputs[:, tout] and g_gin x-slot).  grid = 32 CTAs x 256 thr.
__global__ void k_gates(const float* __restrict__ b_ih,
                        const float* __restrict__ b_hh,
                        const float* __restrict__ hin,
                        float* __restrict__ hout,
                        const float* __restrict__ Wo_w,
                        const float* __restrict__ Wo_b,
                        float* __restrict__ d_outputs,
                        int tout)
{
    __shared__ float so[8][3];
    const int tid = threadIdx.x;
    const int lane = tid & 31, wid = tid >> 5;
    const int g = (blockIdx.x * 256 + tid) << 2;  // element base (step 4)
    const int b = g >> 9, j = g & 511;
    const int gb = b * N3 + j;

    float4 gir = make_float4(b_ih[j], b_ih[j + 1], b_ih[j + 2], b_ih[j + 3]);
    float4 giz = make_float4(b_ih[Dn + j], b_ih[Dn + j + 1],
                             b_ih[Dn + j + 2], b_ih[Dn + j + 3]);
    float4 gnn = make_float4(b_ih[2 * Dn + j], b_ih[2 * Dn + j + 1],
                             b_ih[2 * Dn + j + 2], b_ih[2 * Dn + j + 3]);
    float4 ghr = make_float4(b_hh[j], b_hh[j + 1], b_hh[j + 2], b_hh[j + 3]);
    float4 ghz = make_float4(b_hh[Dn + j], b_hh[Dn + j + 1],
                             b_hh[Dn + j + 2], b_hh[Dn + j + 3]);
    float4 ghn = make_float4(b_hh[2 * Dn + j], b_hh[2 * Dn + j + 1],
                             b_hh[2 * Dn + j + 2], b_hh[2 * Dn + j + 3]);
    #pragma unroll
    for (int p = 0; p < 4; ++p) {
        add4(gir, &g_gipart[p][gb]);
        add4(giz, &g_gipart[p][gb + Dn]);
        add4(gnn, &g_gipart[p][gb + 2 * Dn]);
        add4(ghr, &g_ghpart[p][gb]);
        add4(ghz, &g_ghpart[p][gb + Dn]);
        add4(ghn, &g_ghpart[p][gb + 2 * Dn]);
    }
    float4 h4 = *(const float4*)&hin[g];
    float4 o;
    o.x = gru_one(gir.x, ghr.x, giz.x, ghz.x, gnn.x, ghn.x, h4.x);
    o.y = gru_one(gir.y, ghr.y, giz.y, ghz.y, gnn.y, ghn.y, h4.y);
    o.z = gru_one(gir.z, ghr.z, giz.z, ghz.z, gnn.z, ghn.z, h4.z);
    o.w = gru_one(gir.w, ghr.w, giz.w, ghz.w, gnn.w, ghn.w, h4.w);
    *(float4*)&hout[g] = o;

    // out[b, c] = sum_j h_new[b,j] * Wo[j,c]  (scalar Wo loads; L1-resident)
    const float* wp = &Wo_w[j * 3];
    float p0 = o.x * wp[0] + o.y * wp[3] + o.z * wp[6] + o.w * wp[9];
    float p1 = o.x * wp[1] + o.y * wp[4] + o.z * wp[7] + o.w * wp[10];
    float p2 = o.x * wp[2] + o.y * wp[5] + o.z * wp[8] + o.w * wp[11];
    #pragma unroll
    for (int off = 16; off > 0; off >>= 1) {
        p0 += __shfl_down_sync(0xffffffffu, p0, off);
        p1 += __shfl_down_sync(0xffffffffu, p1, off);
        p2 += __shfl_down_sync(0xffffffffu, p2, off);
    }
    if (lane == 0) { so[wid][0] = p0; so[wid][1] = p1; so[wid][2] = p2; }
    __syncthreads();
    if ((tid & 127) < 3) {
        const int c = tid & 127;
        const int w0i = (tid >> 7) << 2;
        const int bb = blockIdx.x * 2 + (tid >> 7);
        float acc = so[w0i][c] + so[w0i + 1][c] + so[w0i + 2][c] + so[w0i + 3][c]
                  + Wo_b[c];
        d_outputs[((size_t)bb * Tn + tout) * 3 + c] = acc;
        g_gin[bb * GKP + Dn + c] = acc;
    }
}

// q partials (64 CTAs) + gh partials (96 CTAs) — both depend only on h.
__global__ void k_qgh(const float* __restrict__ Wa_w,
                      const float* __restrict__ W_hh)
{
    __shared__ SmemGemm s;
    const int bx = blockIdx.x;
    if (bx < 64) {
        const int part = bx & 7, nt = bx >> 3;
        gemm64<false>(g_h, Dn, Wa_w, Dn, g_qpart[part], Dn, nullptr,
                      0, nt * 64, part * 64, 4, s);
    } else {
        const int i = bx - 64;
        const int part = i & 3, nt = i >> 2;
        gemm64<true>(g_h, Dn, W_hh, Dn, g_ghpart[part], N3, nullptr,
                     0, nt * 64, part * 128, 8, s);
    }
}

// fused per-batch attention: one 1024-thread CTA per batch. scores -> softmax
// -> ctx, all CTA-local (__syncthreads only).  grid = 64.
__global__ void __launch_bounds__(1024, 1)
k_attn(const float* __restrict__ e_all,
       const float* __restrict__ Wa_b,
       const float* __restrict__ Va_w,
       const float* __restrict__ Va_b,
       float* __restrict__ cross, int t)
{
    __shared__ __align__(16) float cpart[8][Dn];   // 16KB, float4-accessed
    __shared__ __align__(16) float qs[Dn];
    __shared__ __align__(16) float vas[Dn];
    __shared__ __align__(16) float ws[Sn];
    __shared__ float red[4];
    __shared__ float smax, sinv;

    const int tid = threadIdx.x;
    const int lane = tid & 31, wid = tid >> 5;
    const int b = blockIdx.x;

    // q = sum of 8 parts + bias (512 threads), Va -> smem
    if (tid < Dn) {
        float q = Wa_b[tid];
        #pragma unroll
        for (int p = 0; p < 8; ++p) q += g_qpart[p][b * Dn + tid];
        qs[tid] = q;
        vas[tid] = Va_w[tid];
    }
    __syncthreads();

    // scores: 32 warps x 4 rows, processed as 2 pairs (2x MLP, deferred reduce)
    const float vb0 = Va_b[0];
    #pragma unroll
    for (int pr = 0; pr < 2; ++pr) {
        const int s0 = (wid << 2) + (pr << 1);
        const float4* ukA = (const float4*)(g_Uk + ((size_t)b * Sn + s0) * Dn);
        const float4* ukB = ukA + (Dn / 4);
        float sum0 = 0.f, sum1 = 0.f;
        #pragma unroll
        for (int i = 0; i < 4; ++i) {
            const int v = lane + (i << 5);
            float4 u0 = ukA[v];
            float4 u1 = ukB[v];
            float4 q4 = *(const float4*)&qs[v << 2];
            float4 a4 = *(const float4*)&vas[v << 2];
            sum0 += tanh_fast(q4.x + u0.x) * a4.x + tanh_fast(q4.y + u0.y) * a4.y
                  + tanh_fast(q4.z + u0.z) * a4.z + tanh_fast(q4.w + u0.w) * a4.w;
            sum1 += tanh_fast(q4.x + u1.x) * a4.x + tanh_fast(q4.y + u1.y) * a4.y
                  + tanh_fast(q4.z + u1.z) * a4.z + tanh_fast(q4.w + u1.w) * a4.w;
        }
        #pragma unroll
        for (int o = 16; o > 0; o >>= 1) {
            sum0 += __shfl_down_sync(0xffffffffu, sum0, o);
            sum1 += __shfl_down_sync(0xffffffffu, sum1, o);
        }
        if (lane == 0) { ws[s0] = sum0 + vb0; ws[s0 + 1] = sum1 + vb0; }
    }
    __syncthreads();

    // softmax over S=128 (first 4 warps)
    float sc = (tid < Sn) ? ws[tid] : -3.4e38f;
    if (tid < Sn) {
        float v = sc;
        #pragma unroll
        for (int o = 16; o > 0; o >>= 1)
            v = fmaxf(v, __shfl_xor_sync(0xffffffffu, v, o));
        if (lane == 0) red[wid] = v;
    }
    __syncthreads();
    if (tid == 0)
        smax = fmaxf(fmaxf(red[0], red[1]), fmaxf(red[2], red[3]));
    __syncthreads();
    float e = 0.f;
    if (tid < Sn) {
        e = __expf(sc - smax);
        float es = e;
        #pragma unroll
        for (int o = 16; o > 0; o >>= 1)
            es += __shfl_xor_sync(0xffffffffu, es, o);
        if (lane == 0) red[wid] = es;
    }
    __syncthreads();
    if (tid == 0)
        sinv = 1.f / (red[0] + red[1] + red[2] + red[3]);
    __syncthreads();
    if (tid < Sn) {
        float w = e * sinv;
        ws[tid] = w;
        cross[((size_t)b * Tn + t) * Sn + tid] = w;
    }
    __syncthreads();

    // ctx: thread handles float4 of d (128 groups), 8 s-groups of 16
    {
        const int d4 = (tid & 127) << 2;
        const int sg = tid >> 7;
        const float4* eb = (const float4*)(e_all + (size_t)b * Sn * Dn + d4);
        float4 a = make_float4(0.f, 0.f, 0.f, 0.f);
        #pragma unroll
        for (int s = sg << 4; s < (sg << 4) + 16; ++s) {
            float4 v = eb[(size_t)s * (Dn / 4)];
            float w = ws[s];
            a.x += w * v.x; a.y += w * v.y; a.z += w * v.z; a.w += w * v.w;
        }
        *(float4*)&cpart[sg][d4] = a;
    }
    __syncthreads();
    if (tid < Dn) {
        float a = 0.f;
        #pragma unroll
        for (int sg = 0; sg < 8; ++sg) a += cpart[sg][tid];
        g_gin[b * GKP + tid] = a;
    }
}

// gi partials = gin @ Wpad^T   (N=1536, K=528, split-K 4).  grid = 96.
__global__ void k_gi()
{
    __shared__ SmemGemm s;
    const int part = blockIdx.x & 3;
    const int nt = blockIdx.x >> 2;
    const int k0 = (part < 3) ? part * 128 : 384;
    const int ki = (part < 3) ? 8 : 9;
    gemm64<true>(g_gin, GKP, g_Wpad, GKP, g_gipart[part], N3, nullptr,
                 0, nt * 64, k0, ki, s);
}

// ---------------- launch ----------------
extern "C" void kernel_launch(void* const* d_in, const int* in_sizes, int n_in,
                              void* d_out, int out_size)
{
    const float* e_all  = (const float*)d_in[0];
    const float* e_last = (const float*)d_in[1];
    const float* Wa_w   = (const float*)d_in[2];
    const float* Wa_b   = (const float*)d_in[3];
    const float* Ua_w   = (const float*)d_in[4];
    const float* Ua_b   = (const float*)d_in[5];
    const float* Va_w   = (const float*)d_in[6];
    const float* Va_b   = (const float*)d_in[7];
    const float* W_ih   = (const float*)d_in[8];
    const float* W_hh   = (const float*)d_in[9];
    const float* b_ih   = (const float*)d_in[10];
    const float* b_hh   = (const float*)d_in[11];
    const float* Wo_w   = (const float*)d_in[12];
    const float* Wo_b   = (const float*)d_in[13];

    float* out       = (float*)d_out;
    float* d_outputs = out;                        // [B,T,3]
    float* hT        = out + Bn * Tn * 3;          // [1,B,D]
    float* cross     = hT + Bn * Dn;               // [B,T,S]

    float* g_h_ptr = nullptr;
    cudaGetSymbolAddress((void**)&g_h_ptr, g_h);

    k_init<<<512, 256>>>(e_last, W_ih);
    k_uk<<<dim3(Dn / 64, (Bn * Sn) / 64), 256>>>(e_all, Ua_w, Ua_b);

    for (int t = 0; t < Tn; ++t) {
        if (t > 0)
            k_gates<<<32, 256>>>(b_ih, b_hh, g_h_ptr, g_h_ptr,
                                 Wo_w, Wo_b, d_outputs, t - 1);
        k_qgh<<<160, 256>>>(Wa_w, W_hh);
        k_attn<<<Bn, 1024>>>(e_all, Wa_b, Va_w, Va_b, cross, t);
        k_gi<<<96, 256>>>();
    }
    k_gates<<<32, 256>>>(b_ih, b_hh, g_h_ptr, hT,
                         Wo_w, Wo_b, d_outputs, Tn - 1);
}

// round 9
// speedup vs baseline: 1.0642x; 1.0642x over previous
#include <cuda_runtime.h>
#include <cstdint>

#define Bn 64
#define Sn 128
#define Dn 512
#define Tn 64
#define N3 1536      // 3*D
#define GK 515       // D + 3
#define GKP 528      // padded to multiple of 16

// ---------------- scratch (device globals; no allocation) ----------------
__device__ float g_Uk[Bn * Sn * Dn];        // [B,S,D] keys projection
__device__ float g_h[Bn * Dn];              // hidden state (in-place update)
__device__ float g_qpart[8][Bn * Dn];       // split-K partials of q
__device__ float g_gipart[4][Bn * N3];      // split-K partials of gi
__device__ float g_ghpart[4][Bn * N3];      // split-K partials of gh
__device__ float g_gin[Bn * GKP];           // [ctx | x | zero-pad]
__device__ float g_Wpad[N3 * GKP];          // W_ih zero-padded to K=528
__device__ float g_scores[Bn * Sn];         // attention scores
__device__ unsigned g_parr[Bn * 32];        // pair-sync arrive (monotonic, replay-safe)
__device__ unsigned g_prel[Bn * 32];        // pair-sync release

__device__ __forceinline__ float tanh_fast(float x) {
    float y; asm("tanh.approx.f32 %0, %1;" : "=f"(y) : "f"(x)); return y;
}

__device__ __forceinline__ float gru_one(float gir, float ghr, float giz, float ghz,
                                         float gnn, float ghn, float h) {
    float r = 1.f / (1.f + __expf(-(gir + ghr)));
    float z = 1.f / (1.f + __expf(-(giz + ghz)));
    float n = tanhf(gnn + r * ghn);
    return (1.f - z) * n + z * h;
}

__device__ __forceinline__ void add4(float4& a, const float* p) {
    float4 v = *(const float4*)p;
    a.x += v.x; a.y += v.y; a.z += v.z; a.w += v.w;
}

struct SmemGemm { float As[16][68]; float Bs[16][68]; };

// C[64 x 64] tile of  C = A(MxK) * B  (+bias), BK=16, 256 threads, 4x4 microtile.
// NT=false: B row-major [K,N];  NT=true: B row-major [N,K].
template <bool NT>
__device__ __forceinline__ void gemm64(const float* __restrict__ A, int lda,
                                       const float* __restrict__ B, int ldb,
                                       float* __restrict__ C, int ldc,
                                       const float* __restrict__ bias,
                                       int m0, int n0, int k0, int kiters,
                                       SmemGemm& s)
{
    const int tid = threadIdx.x;
    const int tx = tid & 15, ty = tid >> 4;
    const int am = tid >> 2, ak = (tid & 3) << 2;
    float acc[4][4] = {};

    for (int it = 0; it < kiters; ++it) {
        const int k = k0 + it * 16;
        float4 a4 = *(const float4*)&A[(size_t)(m0 + am) * lda + k + ak];
        float4 b4;
        if (NT) {
            b4 = *(const float4*)&B[(size_t)(n0 + am) * ldb + k + ak];
        } else {
            const int bk = tid >> 4, bn = (tid & 15) << 2;
            b4 = *(const float4*)&B[(size_t)(k + bk) * ldb + n0 + bn];
        }
        __syncthreads();
        s.As[ak + 0][am] = a4.x; s.As[ak + 1][am] = a4.y;
        s.As[ak + 2][am] = a4.z; s.As[ak + 3][am] = a4.w;
        if (NT) {
            s.Bs[ak + 0][am] = b4.x; s.Bs[ak + 1][am] = b4.y;
            s.Bs[ak + 2][am] = b4.z; s.Bs[ak + 3][am] = b4.w;
        } else {
            const int bk = tid >> 4, bn = (tid & 15) << 2;
            *(float4*)&s.Bs[bk][bn] = b4;
        }
        __syncthreads();
        #pragma unroll
        for (int kk = 0; kk < 16; ++kk) {
            float4 av = *(const float4*)&s.As[kk][ty << 2];
            float4 bv = *(const float4*)&s.Bs[kk][tx << 2];
            float a[4] = {av.x, av.y, av.z, av.w};
            float b[4] = {bv.x, bv.y, bv.z, bv.w};
            #pragma unroll
            for (int u = 0; u < 4; ++u)
                #pragma unroll
                for (int v = 0; v < 4; ++v)
                    acc[u][v] += a[u] * b[v];
        }
    }

    float4 bi = make_float4(0.f, 0.f, 0.f, 0.f);
    if (bias) bi = *(const float4*)&bias[n0 + (tx << 2)];
    #pragma unroll
    for (int u = 0; u < 4; ++u) {
        float4 o;
        o.x = acc[u][0] + bi.x; o.y = acc[u][1] + bi.y;
        o.z = acc[u][2] + bi.z; o.w = acc[u][3] + bi.w;
        *(float4*)&C[(size_t)(m0 + (ty << 2) + u) * ldc + n0 + (tx << 2)] = o;
    }
}

// ---------------- kernels ----------------

__global__ void k_init(const float* __restrict__ e_last,
                       const float* __restrict__ W_ih)
{
    const int i = blockIdx.x * blockDim.x + threadIdx.x;
    const int stride = gridDim.x * blockDim.x;
    if (i < Bn * Dn) g_h[i] = e_last[i];
    if (i < Bn * 16) {                     // zero x + pad region of gin
        int b = i >> 4, k = i & 15;
        g_gin[b * GKP + Dn + k] = 0.f;
    }
    for (int j = i; j < N3 * GKP; j += stride) {
        int n = j / GKP, k = j - n * GKP;
        g_Wpad[j] = (k < GK) ? W_ih[n * GK + k] : 0.f;
    }
}

// Uk = e_all @ Ua_w + Ua_b    (M = B*S = 8192, N = K = 512)
__global__ void k_uk(const float* __restrict__ e_all,
                     const float* __restrict__ Ua_w,
                     const float* __restrict__ Ua_b)
{
    __shared__ SmemGemm s;
    gemm64<false>(e_all, Dn, Ua_w, Dn, g_Uk, Dn, Ua_b,
                  blockIdx.y * 64, blockIdx.x * 64, 0, 32, s);
}

// GRU gates: h(in)+parts -> h(out), PLUS out = h_new @ Wo + b.  grid = 32 CTAs.
__global__ void k_gates(const float* __restrict__ b_ih,
                        const float* __restrict__ b_hh,
                        const float* __restrict__ hin,
                        float* __restrict__ hout,
                        const float* __restrict__ Wo_w,
                        const float* __restrict__ Wo_b,
                        float* __restrict__ d_outputs,
                        int tout)
{
    __shared__ float so[8][3];
    const int tid = threadIdx.x;
    const int lane = tid & 31, wid = tid >> 5;
    const int g = (blockIdx.x * 256 + tid) << 2;  // element base (step 4)
    const int b = g >> 9, j = g & 511;
    const int gb = b * N3 + j;

    float4 gir = make_float4(b_ih[j], b_ih[j + 1], b_ih[j + 2], b_ih[j + 3]);
    float4 giz = make_float4(b_ih[Dn + j], b_ih[Dn + j + 1],
                             b_ih[Dn + j + 2], b_ih[Dn + j + 3]);
    float4 gnn = make_float4(b_ih[2 * Dn + j], b_ih[2 * Dn + j + 1],
                             b_ih[2 * Dn + j + 2], b_ih[2 * Dn + j + 3]);
    float4 ghr = make_float4(b_hh[j], b_hh[j + 1], b_hh[j + 2], b_hh[j + 3]);
    float4 ghz = make_float4(b_hh[Dn + j], b_hh[Dn + j + 1],
                             b_hh[Dn + j + 2], b_hh[Dn + j + 3]);
    float4 ghn = make_float4(b_hh[2 * Dn + j], b_hh[2 * Dn + j + 1],
                             b_hh[2 * Dn + j + 2], b_hh[2 * Dn + j + 3]);
    #pragma unroll
    for (int p = 0; p < 4; ++p) {
        add4(gir, &g_gipart[p][gb]);
        add4(giz, &g_gipart[p][gb + Dn]);
        add4(gnn, &g_gipart[p][gb + 2 * Dn]);
        add4(ghr, &g_ghpart[p][gb]);
        add4(ghz, &g_ghpart[p][gb + Dn]);
        add4(ghn, &g_ghpart[p][gb + 2 * Dn]);
    }
    float4 h4 = *(const float4*)&hin[g];
    float4 o;
    o.x = gru_one(gir.x, ghr.x, giz.x, ghz.x, gnn.x, ghn.x, h4.x);
    o.y = gru_one(gir.y, ghr.y, giz.y, ghz.y, gnn.y, ghn.y, h4.y);
    o.z = gru_one(gir.z, ghr.z, giz.z, ghz.z, gnn.z, ghn.z, h4.z);
    o.w = gru_one(gir.w, ghr.w, giz.w, ghz.w, gnn.w, ghn.w, h4.w);
    *(float4*)&hout[g] = o;

    // out[b, c] = sum_j h_new[b,j] * Wo[j,c]
    const float* wp = &Wo_w[j * 3];
    float p0 = o.x * wp[0] + o.y * wp[3] + o.z * wp[6] + o.w * wp[9];
    float p1 = o.x * wp[1] + o.y * wp[4] + o.z * wp[7] + o.w * wp[10];
    float p2 = o.x * wp[2] + o.y * wp[5] + o.z * wp[8] + o.w * wp[11];
    #pragma unroll
    for (int off = 16; off > 0; off >>= 1) {
        p0 += __shfl_down_sync(0xffffffffu, p0, off);
        p1 += __shfl_down_sync(0xffffffffu, p1, off);
        p2 += __shfl_down_sync(0xffffffffu, p2, off);
    }
    if (lane == 0) { so[wid][0] = p0; so[wid][1] = p1; so[wid][2] = p2; }
    __syncthreads();
    if ((tid & 127) < 3) {
        const int c = tid & 127;
        const int w0i = (tid >> 7) << 2;
        const int bb = blockIdx.x * 2 + (tid >> 7);
        float acc = so[w0i][c] + so[w0i + 1][c] + so[w0i + 2][c] + so[w0i + 3][c]
                  + Wo_b[c];
        d_outputs[((size_t)bb * Tn + tout) * 3 + c] = acc;
        g_gin[bb * GKP + Dn + c] = acc;
    }
}

// q partials = h @ Wa  (N=512, split-K 8).  grid = 64 CTAs (8 nt x 8 parts).
__global__ void k_q(const float* __restrict__ Wa_w)
{
    __shared__ SmemGemm s;
    const int part = blockIdx.x & 7, nt = blockIdx.x >> 3;
    gemm64<false>(g_h, Dn, Wa_w, Dn, g_qpart[part], Dn, nullptr,
                  0, nt * 64, part * 64, 4, s);
}

// fused attention: 2 CTAs per batch (grid = 128), 1024 threads.
// Each CTA: q-sum -> 64 score rows -> pair sync -> softmax -> 256 ctx cols.
__global__ void __launch_bounds__(1024, 1)
k_attn(const float* __restrict__ e_all,
       const float* __restrict__ Wa_b,
       const float* __restrict__ Va_w,
       const float* __restrict__ Va_b,
       float* __restrict__ cross, int t)
{
    __shared__ __align__(16) float cpart[16][256];  // 16KB, float4-accessed
    __shared__ __align__(16) float qs[Dn];
    __shared__ __align__(16) float vas[Dn];
    __shared__ __align__(16) float ws[Sn];
    __shared__ float red[4];
    __shared__ float smax, sinv;

    const int tid = threadIdx.x;
    const int lane = tid & 31, wid = tid >> 5;
    const int b = blockIdx.x >> 1, half = blockIdx.x & 1;

    // q = sum of 8 parts + bias (512 threads), Va -> smem (redundant per pair)
    if (tid < Dn) {
        float q = Wa_b[tid];
        #pragma unroll
        for (int p = 0; p < 8; ++p) q += g_qpart[p][b * Dn + tid];
        qs[tid] = q;
        vas[tid] = Va_w[tid];
    }
    __syncthreads();

    // scores: 64 rows per CTA, 2 per warp
    const float vb0 = Va_b[0];
    #pragma unroll
    for (int r = 0; r < 2; ++r) {
        const int s = half * 64 + (wid << 1) + r;
        const float4* uk4 = (const float4*)(g_Uk + ((size_t)b * Sn + s) * Dn);
        float sum = 0.f;
        #pragma unroll
        for (int i = 0; i < 4; ++i) {
            const int v = lane + (i << 5);
            float4 u = uk4[v];
            float4 q4 = *(const float4*)&qs[v << 2];
            float4 a4 = *(const float4*)&vas[v << 2];
            sum += tanh_fast(q4.x + u.x) * a4.x;
            sum += tanh_fast(q4.y + u.y) * a4.y;
            sum += tanh_fast(q4.z + u.z) * a4.z;
            sum += tanh_fast(q4.w + u.w) * a4.w;
        }
        #pragma unroll
        for (int o = 16; o > 0; o >>= 1)
            sum += __shfl_down_sync(0xffffffffu, sum, o);
        if (lane == 0) g_scores[b * Sn + s] = sum + vb0;
    }

    // pair sync (replay-safe monotonic counters, one pair per batch)
    __syncthreads();
    if (tid == 0) {
        __threadfence();
        unsigned old;
        asm volatile("atom.acq_rel.gpu.add.u32 %0, [%1], 1;"
                     : "=r"(old) : "l"(&g_parr[b * 32]) : "memory");
        const unsigned k = old >> 1;
        if (old & 1u) {
            asm volatile("st.release.gpu.u32 [%0], %1;"
                         :: "l"(&g_prel[b * 32]), "r"(k + 1) : "memory");
        } else {
            unsigned r;
            do {
                asm volatile("ld.acquire.gpu.u32 %0, [%1];"
                             : "=r"(r) : "l"(&g_prel[b * 32]) : "memory");
            } while (r < k + 1);
        }
    }
    __syncthreads();

    // softmax over S=128 (redundant per pair; first 4 warps)
    float sc = (tid < Sn) ? __ldcg(&g_scores[b * Sn + tid]) : -3.4e38f;
    if (tid < Sn) {
        float v = sc;
        #pragma unroll
        for (int o = 16; o > 0; o >>= 1)
            v = fmaxf(v, __shfl_xor_sync(0xffffffffu, v, o));
        if (lane == 0) red[wid] = v;
    }
    __syncthreads();
    if (tid == 0)
        smax = fmaxf(fmaxf(red[0], red[1]), fmaxf(red[2], red[3]));
    __syncthreads();
    float e = 0.f;
    if (tid < Sn) {
        e = __expf(sc - smax);
        float es = e;
        #pragma unroll
        for (int o = 16; o > 0; o >>= 1)
            es += __shfl_xor_sync(0xffffffffu, es, o);
        if (lane == 0) red[wid] = es;
    }
    __syncthreads();
    if (tid == 0)
        sinv = 1.f / (red[0] + red[1] + red[2] + red[3]);
    __syncthreads();
    if (tid < Sn) {
        float w = e * sinv;
        ws[tid] = w;
        if (half == 0) cross[((size_t)b * Tn + t) * Sn + tid] = w;
    }
    __syncthreads();

    // ctx: this CTA covers d in [half*256, half*256+256).
    // 64 float4 col-groups x 16 s-groups of 8.
    {
        const int dg = tid & 63, sg = tid >> 6;
        const int d = half * 256 + (dg << 2);
        const float4* eb = (const float4*)(e_all + (size_t)b * Sn * Dn + d);
        float4 a = make_float4(0.f, 0.f, 0.f, 0.f);
        #pragma unroll
        for (int s = sg << 3; s < (sg << 3) + 8; ++s) {
            float4 v = eb[(size_t)s * (Dn / 4)];
            float w = ws[s];
            a.x += w * v.x; a.y += w * v.y; a.z += w * v.z; a.w += w * v.w;
        }
        *(float4*)&cpart[sg][dg << 2] = a;
    }
    __syncthreads();
    if (tid < 256) {
        float a = 0.f;
        #pragma unroll
        for (int sg = 0; sg < 16; ++sg) a += cpart[sg][tid];
        g_gin[b * GKP + half * 256 + tid] = a;
    }
}

// gi partials (96 CTAs) + gh partials (96 CTAs) in one launch
__global__ void k_gigh(const float* __restrict__ W_hh)
{
    __shared__ SmemGemm s;
    const int bx = blockIdx.x;
    if (bx < 96) {
        const int part = bx & 3, nt = bx >> 2;
        const int k0 = (part < 3) ? part * 128 : 384;
        const int ki = (part < 3) ? 8 : 9;
        gemm64<true>(g_gin, GKP, g_Wpad, GKP, g_gipart[part], N3, nullptr,
                     0, nt * 64, k0, ki, s);
    } else {
        const int i = bx - 96;
        const int part = i & 3, nt = i >> 2;
        gemm64<true>(g_h, Dn, W_hh, Dn, g_ghpart[part], N3, nullptr,
                     0, nt * 64, part * 128, 8, s);
    }
}

// ---------------- launch ----------------
extern "C" void kernel_launch(void* const* d_in, const int* in_sizes, int n_in,
                              void* d_out, int out_size)
{
    const float* e_all  = (const float*)d_in[0];
    const float* e_last = (const float*)d_in[1];
    const float* Wa_w   = (const float*)d_in[2];
    const float* Wa_b   = (const float*)d_in[3];
    const float* Ua_w   = (const float*)d_in[4];
    const float* Ua_b   = (const float*)d_in[5];
    const float* Va_w   = (const float*)d_in[6];
    const float* Va_b   = (const float*)d_in[7];
    const float* W_ih   = (const float*)d_in[8];
    const float* W_hh   = (const float*)d_in[9];
    const float* b_ih   = (const float*)d_in[10];
    const float* b_hh   = (const float*)d_in[11];
    const float* Wo_w   = (const float*)d_in[12];
    const float* Wo_b   = (const float*)d_in[13];

    float* out       = (float*)d_out;
    float* d_outputs = out;                        // [B,T,3]
    float* hT        = out + Bn * Tn * 3;          // [1,B,D]
    float* cross     = hT + Bn * Dn;               // [B,T,S]

    float* g_h_ptr = nullptr;
    cudaGetSymbolAddress((void**)&g_h_ptr, g_h);

    k_init<<<512, 256>>>(e_last, W_ih);
    k_uk<<<dim3(Dn / 64, (Bn * Sn) / 64), 256>>>(e_all, Ua_w, Ua_b);

    for (int t = 0; t < Tn; ++t) {
        if (t > 0)
            k_gates<<<32, 256>>>(b_ih, b_hh, g_h_ptr, g_h_ptr,
                                 Wo_w, Wo_b, d_outputs, t - 1);
        k_q<<<64, 256>>>(Wa_w);
        k_attn<<<Bn * 2, 1024>>>(e_all, Wa_b, Va_w, Va_b, cross, t);
        k_gigh<<<192, 256>>>(W_hh);
    }
    k_gates<<<32, 256>>>(b_ih, b_hh, g_h_ptr, hT,
                         Wo_w, Wo_b, d_outputs, Tn - 1);
}

// round 10
// speedup vs baseline: 1.1314x; 1.0631x over previous
#include <cuda_runtime.h>
#include <cstdint>

#define Bn 64
#define Sn 128
#define Dn 512
#define Tn 64
#define N3 1536      // 3*D
#define GK 515       // D + 3
#define GKP 528      // padded to multiple of 16

// ---------------- scratch (device globals; no allocation) ----------------
__device__ float g_Uk[Bn * Sn * Dn];        // [B,S,D] keys projection
__device__ float g_h[Bn * Dn];              // hidden state (in-place update)
__device__ float g_qpart[8][Bn * Dn];       // split-K partials of q
__device__ float g_gipart[4][Bn * N3];      // split-K partials of gi
__device__ float g_ghpart[4][Bn * N3];      // split-K partials of gh
__device__ float g_gin[Bn * GKP];           // [ctx | x | zero-pad]
__device__ float g_Wpad[N3 * GKP];          // W_ih zero-padded to K=528

__device__ __forceinline__ float tanh_fast(float x) {
    float y; asm("tanh.approx.f32 %0, %1;" : "=f"(y) : "f"(x)); return y;
}

__device__ __forceinline__ void prefetch_L1(const void* p) {
    asm volatile("prefetch.global.L1 [%0];" :: "l"(p));
}

__device__ __forceinline__ float gru_one(float gir, float ghr, float giz, float ghz,
                                         float gnn, float ghn, float h) {
    float r = 1.f / (1.f + __expf(-(gir + ghr)));
    float z = 1.f / (1.f + __expf(-(giz + ghz)));
    float n = tanhf(gnn + r * ghn);
    return (1.f - z) * n + z * h;
}

__device__ __forceinline__ void add4(float4& a, const float* p) {
    float4 v = *(const float4*)p;
    a.x += v.x; a.y += v.y; a.z += v.z; a.w += v.w;
}

struct SmemGemm { float As[16][68]; float Bs[16][68]; };

// C[64 x 64] tile of  C = A(MxK) * B  (+bias), BK=16, 256 threads, 4x4 microtile.
// NT=false: B row-major [K,N];  NT=true: B row-major [N,K].
template <bool NT>
__device__ __forceinline__ void gemm64(const float* __restrict__ A, int lda,
                                       const float* __restrict__ B, int ldb,
                                       float* __restrict__ C, int ldc,
                                       const float* __restrict__ bias,
                                       int m0, int n0, int k0, int kiters,
                                       SmemGemm& s)
{
    const int tid = threadIdx.x;
    const int tx = tid & 15, ty = tid >> 4;
    const int am = tid >> 2, ak = (tid & 3) << 2;
    float acc[4][4] = {};

    for (int it = 0; it < kiters; ++it) {
        const int k = k0 + it * 16;
        float4 a4 = *(const float4*)&A[(size_t)(m0 + am) * lda + k + ak];
        float4 b4;
        if (NT) {
            b4 = *(const float4*)&B[(size_t)(n0 + am) * ldb + k + ak];
        } else {
            const int bk = tid >> 4, bn = (tid & 15) << 2;
            b4 = *(const float4*)&B[(size_t)(k + bk) * ldb + n0 + bn];
        }
        __syncthreads();
        s.As[ak + 0][am] = a4.x; s.As[ak + 1][am] = a4.y;
        s.As[ak + 2][am] = a4.z; s.As[ak + 3][am] = a4.w;
        if (NT) {
            s.Bs[ak + 0][am] = b4.x; s.Bs[ak + 1][am] = b4.y;
            s.Bs[ak + 2][am] = b4.z; s.Bs[ak + 3][am] = b4.w;
        } else {
            const int bk = tid >> 4, bn = (tid & 15) << 2;
            *(float4*)&s.Bs[bk][bn] = b4;
        }
        __syncthreads();
        #pragma unroll
        for (int kk = 0; kk < 16; ++kk) {
            float4 av = *(const float4*)&s.As[kk][ty << 2];
            float4 bv = *(const float4*)&s.Bs[kk][tx << 2];
            float a[4] = {av.x, av.y, av.z, av.w};
            float b[4] = {bv.x, bv.y, bv.z, bv.w};
            #pragma unroll
            for (int u = 0; u < 4; ++u)
                #pragma unroll
                for (int v = 0; v < 4; ++v)
                    acc[u][v] += a[u] * b[v];
        }
    }

    float4 bi = make_float4(0.f, 0.f, 0.f, 0.f);
    if (bias) bi = *(const float4*)&bias[n0 + (tx << 2)];
    #pragma unroll
    for (int u = 0; u < 4; ++u) {
        float4 o;
        o.x = acc[u][0] + bi.x; o.y = acc[u][1] + bi.y;
        o.z = acc[u][2] + bi.z; o.w = acc[u][3] + bi.w;
        *(float4*)&C[(size_t)(m0 + (ty << 2) + u) * ldc + n0 + (tx << 2)] = o;
    }
}

// ---------------- kernels ----------------

__global__ void k_init(const float* __restrict__ e_last,
                       const float* __restrict__ W_ih)
{
    const int i = blockIdx.x * blockDim.x + threadIdx.x;
    const int stride = gridDim.x * blockDim.x;
    if (i < Bn * Dn) g_h[i] = e_last[i];
    if (i < Bn * 16) {                     // zero x + pad region of gin
        int b = i >> 4, k = i & 15;
        g_gin[b * GKP + Dn + k] = 0.f;
    }
    for (int j = i; j < N3 * GKP; j += stride) {
        int n = j / GKP, k = j - n * GKP;
        g_Wpad[j] = (k < GK) ? W_ih[n * GK + k] : 0.f;
    }
}

// Uk = e_all @ Ua_w + Ua_b    (M = B*S = 8192, N = K = 512)
__global__ void k_uk(const float* __restrict__ e_all,
                     const float* __restrict__ Ua_w,
                     const float* __restrict__ Ua_b)
{
    __shared__ SmemGemm s;
    gemm64<false>(e_all, Dn, Ua_w, Dn, g_Uk, Dn, Ua_b,
                  blockIdx.y * 64, blockIdx.x * 64, 0, 32, s);
}

// GRU gates: h(in)+parts -> h(out), PLUS out = h_new @ Wo + b.  grid = 32 CTAs.
__global__ void k_gates(const float* __restrict__ b_ih,
                        const float* __restrict__ b_hh,
                        const float* __restrict__ hin,
                        float* __restrict__ hout,
                        const float* __restrict__ Wo_w,
                        const float* __restrict__ Wo_b,
                        float* __restrict__ d_outputs,
                        int tout)
{
    __shared__ float so[8][3];
    const int tid = threadIdx.x;
    const int lane = tid & 31, wid = tid >> 5;
    const int g = (blockIdx.x * 256 + tid) << 2;  // element base (step 4)
    const int b = g >> 9, j = g & 511;
    const int gb = b * N3 + j;

    // ---- static prologue (overlaps predecessor via PDL) ----
    if (tid < 48) prefetch_L1(&Wo_w[tid * 32]);
    float4 gir = make_float4(b_ih[j], b_ih[j + 1], b_ih[j + 2], b_ih[j + 3]);
    float4 giz = make_float4(b_ih[Dn + j], b_ih[Dn + j + 1],
                             b_ih[Dn + j + 2], b_ih[Dn + j + 3]);
    float4 gnn = make_float4(b_ih[2 * Dn + j], b_ih[2 * Dn + j + 1],
                             b_ih[2 * Dn + j + 2], b_ih[2 * Dn + j + 3]);
    float4 ghr = make_float4(b_hh[j], b_hh[j + 1], b_hh[j + 2], b_hh[j + 3]);
    float4 ghz = make_float4(b_hh[Dn + j], b_hh[Dn + j + 1],
                             b_hh[Dn + j + 2], b_hh[Dn + j + 3]);
    float4 ghn = make_float4(b_hh[2 * Dn + j], b_hh[2 * Dn + j + 1],
                             b_hh[2 * Dn + j + 2], b_hh[2 * Dn + j + 3]);

    cudaGridDependencySynchronize();

    #pragma unroll
    for (int p = 0; p < 4; ++p) {
        add4(gir, &g_gipart[p][gb]);
        add4(giz, &g_gipart[p][gb + Dn]);
        add4(gnn, &g_gipart[p][gb + 2 * Dn]);
        add4(ghr, &g_ghpart[p][gb]);
        add4(ghz, &g_ghpart[p][gb + Dn]);
        add4(ghn, &g_ghpart[p][gb + 2 * Dn]);
    }
    float4 h4 = *(const float4*)&hin[g];
    float4 o;
    o.x = gru_one(gir.x, ghr.x, giz.x, ghz.x, gnn.x, ghn.x, h4.x);
    o.y = gru_one(gir.y, ghr.y, giz.y, ghz.y, gnn.y, ghn.y, h4.y);
    o.z = gru_one(gir.z, ghr.z, giz.z, ghz.z, gnn.z, ghn.z, h4.z);
    o.w = gru_one(gir.w, ghr.w, giz.w, ghz.w, gnn.w, ghn.w, h4.w);
    *(float4*)&hout[g] = o;

    // out[b, c] = sum_j h_new[b,j] * Wo[j,c]
    const float* wp = &Wo_w[j * 3];
    float p0 = o.x * wp[0] + o.y * wp[3] + o.z * wp[6] + o.w * wp[9];
    float p1 = o.x * wp[1] + o.y * wp[4] + o.z * wp[7] + o.w * wp[10];
    float p2 = o.x * wp[2] + o.y * wp[5] + o.z * wp[8] + o.w * wp[11];
    #pragma unroll
    for (int off = 16; off > 0; off >>= 1) {
        p0 += __shfl_down_sync(0xffffffffu, p0, off);
        p1 += __shfl_down_sync(0xffffffffu, p1, off);
        p2 += __shfl_down_sync(0xffffffffu, p2, off);
    }
    if (lane == 0) { so[wid][0] = p0; so[wid][1] = p1; so[wid][2] = p2; }
    __syncthreads();
    if ((tid & 127) < 3) {
        const int c = tid & 127;
        const int w0i = (tid >> 7) << 2;
        const int bb = blockIdx.x * 2 + (tid >> 7);
        float acc = so[w0i][c] + so[w0i + 1][c] + so[w0i + 2][c] + so[w0i + 3][c]
                  + Wo_b[c];
        d_outputs[((size_t)bb * Tn + tout) * 3 + c] = acc;
        g_gin[bb * GKP + Dn + c] = acc;
    }
    cudaTriggerProgrammaticLaunchCompletion();
}

// q partials = h @ Wa  (N=512, split-K 8).  grid = 64 CTAs (8 nt x 8 parts).
__global__ void k_q(const float* __restrict__ Wa_w)
{
    __shared__ SmemGemm s;
    const int part = blockIdx.x & 7, nt = blockIdx.x >> 3;
    const int tid = threadIdx.x;

    // prologue: prefetch static B tile (64k x 64n region of Wa)
    if (tid < 128) {
        const int r = tid >> 1, c = (tid & 1) << 5;
        prefetch_L1(&Wa_w[(size_t)(part * 64 + r) * Dn + nt * 64 + c]);
    }
    cudaGridDependencySynchronize();

    gemm64<false>(g_h, Dn, Wa_w, Dn, g_qpart[part], Dn, nullptr,
                  0, nt * 64, part * 64, 4, s);
    cudaTriggerProgrammaticLaunchCompletion();
}

// fused per-batch attention: one 1024-thread CTA per batch. scores -> softmax
// -> ctx, all CTA-local (__syncthreads only).  grid = 64.
__global__ void __launch_bounds__(1024, 1)
k_attn(const float* __restrict__ e_all,
       const float* __restrict__ Wa_b,
       const float* __restrict__ Va_w,
       const float* __restrict__ Va_b,
       float* __restrict__ cross, int t)
{
    __shared__ __align__(16) float cpart[8][Dn];   // 16KB, float4-accessed
    __shared__ __align__(16) float qs[Dn];
    __shared__ __align__(16) float vas[Dn];
    __shared__ __align__(16) float ws[Sn];
    __shared__ float red[4];
    __shared__ float smax, sinv;

    const int tid = threadIdx.x;
    const int lane = tid & 31, wid = tid >> 5;
    const int b = blockIdx.x;
    const float* ukb = g_Uk + (size_t)b * Sn * Dn;

    // ---- static prologue: warm L1 with this batch's Uk slice (256KB).
    // Guarded t>0: at t=0 k_uk may still be writing (L1 is not coherent).
    if (t > 0) {
        prefetch_L1(ukb + (size_t)tid * 32);
        prefetch_L1(ukb + (size_t)(tid + 1024) * 32);
    }
    float qb = 0.f, vaw = 0.f;
    if (tid < Dn) { qb = Wa_b[tid]; vaw = Va_w[tid]; }
    const float vb0 = Va_b[0];

    cudaGridDependencySynchronize();

    // q = sum of 8 parts + bias (512 threads), Va -> smem
    if (tid < Dn) {
        float q = qb;
        #pragma unroll
        for (int p = 0; p < 8; ++p) q += g_qpart[p][b * Dn + tid];
        qs[tid] = q;
        vas[tid] = vaw;
    }
    __syncthreads();

    // scores: 32 warps x 4 rows
    #pragma unroll
    for (int r = 0; r < 4; ++r) {
        const int s = (wid << 2) + r;
        const float4* uk4 = (const float4*)(ukb + (size_t)s * Dn);
        float sum = 0.f;
        #pragma unroll
        for (int i = 0; i < 4; ++i) {
            const int v = lane + (i << 5);
            float4 u = uk4[v];
            float4 q4 = *(const float4*)&qs[v << 2];
            float4 a4 = *(const float4*)&vas[v << 2];
            sum += tanh_fast(q4.x + u.x) * a4.x;
            sum += tanh_fast(q4.y + u.y) * a4.y;
            sum += tanh_fast(q4.z + u.z) * a4.z;
            sum += tanh_fast(q4.w + u.w) * a4.w;
        }
        #pragma unroll
        for (int o = 16; o > 0; o >>= 1)
            sum += __shfl_down_sync(0xffffffffu, sum, o);
        if (lane == 0) ws[s] = sum + vb0;
    }
    __syncthreads();

    // softmax over S=128 (first 4 warps)
    float sc = (tid < Sn) ? ws[tid] : -3.4e38f;
    if (tid < Sn) {
        float v = sc;
        #pragma unroll
        for (int o = 16; o > 0; o >>= 1)
            v = fmaxf(v, __shfl_xor_sync(0xffffffffu, v, o));
        if (lane == 0) red[wid] = v;
    }
    __syncthreads();
    if (tid == 0)
        smax = fmaxf(fmaxf(red[0], red[1]), fmaxf(red[2], red[3]));
    __syncthreads();
    float e = 0.f;
    if (tid < Sn) {
        e = __expf(sc - smax);
        float es = e;
        #pragma unroll
        for (int o = 16; o > 0; o >>= 1)
            es += __shfl_xor_sync(0xffffffffu, es, o);
        if (lane == 0) red[wid] = es;
    }
    __syncthreads();
    if (tid == 0)
        sinv = 1.f / (red[0] + red[1] + red[2] + red[3]);
    __syncthreads();
    if (tid < Sn) {
        float w = e * sinv;
        ws[tid] = w;
        cross[((size_t)b * Tn + t) * Sn + tid] = w;
    }
    __syncthreads();

    // ctx: thread handles float4 of d (128 groups), 8 s-groups of 16
    {
        const int d4 = (tid & 127) << 2;
        const int sg = tid >> 7;
        const float4* eb = (const float4*)(e_all + (size_t)b * Sn * Dn + d4);
        float4 a = make_float4(0.f, 0.f, 0.f, 0.f);
        #pragma unroll
        for (int s = sg << 4; s < (sg << 4) + 16; ++s) {
            float4 v = eb[(size_t)s * (Dn / 4)];
            float w = ws[s];
            a.x += w * v.x; a.y += w * v.y; a.z += w * v.z; a.w += w * v.w;
        }
        *(float4*)&cpart[sg][d4] = a;
    }
    __syncthreads();
    if (tid < Dn) {
        float a = 0.f;
        #pragma unroll
        for (int sg = 0; sg < 8; ++sg) a += cpart[sg][tid];
        g_gin[b * GKP + tid] = a;
    }
    cudaTriggerProgrammaticLaunchCompletion();
}

// gi partials (96 CTAs) + gh partials (96 CTAs) in one launch
__global__ void k_gigh(const float* __restrict__ W_hh)
{
    __shared__ SmemGemm s;
    const int bx = blockIdx.x;
    const int tid = threadIdx.x;
    if (bx < 96) {
        const int part = bx & 3, nt = bx >> 2;
        const int k0 = (part < 3) ? part * 128 : 384;
        const int ki = (part < 3) ? 8 : 9;
        // prologue: prefetch static Wpad slice (rows nt*64.., cols k0..)
        for (int i = tid; i < 320; i += 256) {
            const int r = i / 5, o = i - r * 5;
            prefetch_L1(&g_Wpad[(size_t)(nt * 64 + r) * GKP + k0 + o * 32]);
        }
        cudaGridDependencySynchronize();
        gemm64<true>(g_gin, GKP, g_Wpad, GKP, g_gipart[part], N3, nullptr,
                     0, nt * 64, k0, ki, s);
    } else {
        const int i = bx - 96;
        const int part = i & 3, nt = i >> 2;
        // prologue: prefetch static W_hh slice
        {
            const int r = tid >> 2, o = tid & 3;
            prefetch_L1(&W_hh[(size_t)(nt * 64 + r) * Dn + part * 128 + o * 32]);
        }
        cudaGridDependencySynchronize();
        gemm64<true>(g_h, Dn, W_hh, Dn, g_ghpart[part], N3, nullptr,
                     0, nt * 64, part * 128, 8, s);
    }
    cudaTriggerProgrammaticLaunchCompletion();
}

// ---------------- launch helpers ----------------
template <typename F, typename... Args>
static inline void pdl_launch(F* kern, dim3 grid, dim3 block, Args... args)
{
    cudaLaunchConfig_t cfg = {};
    cfg.gridDim = grid;
    cfg.blockDim = block;
    cfg.dynamicSmemBytes = 0;
    cfg.stream = 0;
    cudaLaunchAttribute attr = {};
    attr.id = cudaLaunchAttributeProgrammaticStreamSerialization;
    attr.val.programmaticStreamSerializationAllowed = 1;
    cfg.attrs = &attr;
    cfg.numAttrs = 1;
    cudaLaunchKernelEx(&cfg, kern, args...);
}

// ---------------- launch ----------------
extern "C" void kernel_launch(void* const* d_in, const int* in_sizes, int n_in,
                              void* d_out, int out_size)
{
    const float* e_all  = (const float*)d_in[0];
    const float* e_last = (const float*)d_in[1];
    const float* Wa_w   = (const float*)d_in[2];
    const float* Wa_b   = (const float*)d_in[3];
    const float* Ua_w   = (const float*)d_in[4];
    const float* Ua_b   = (const float*)d_in[5];
    const float* Va_w   = (const float*)d_in[6];
    const float* Va_b   = (const float*)d_in[7];
    const float* W_ih   = (const float*)d_in[8];
    const float* W_hh   = (const float*)d_in[9];
    const float* b_ih   = (const float*)d_in[10];
    const float* b_hh   = (const float*)d_in[11];
    const float* Wo_w   = (const float*)d_in[12];
    const float* Wo_b   = (const float*)d_in[13];

    float* out       = (float*)d_out;
    float* d_outputs = out;                        // [B,T,3]
    float* hT        = out + Bn * Tn * 3;          // [1,B,D]
    float* cross     = hT + Bn * Dn;               // [B,T,S]

    float* g_h_ptr = nullptr;
    cudaGetSymbolAddress((void**)&g_h_ptr, g_h);

    k_init<<<512, 256>>>(e_last, W_ih);
    k_uk<<<dim3(Dn / 64, (Bn * Sn) / 64), 256>>>(e_all, Ua_w, Ua_b);

    for (int t = 0; t < Tn; ++t) {
        if (t > 0)
            pdl_launch(k_gates, dim3(32), dim3(256),
                       b_ih, b_hh, (const float*)g_h_ptr, g_h_ptr,
                       Wo_w, Wo_b, d_outputs, t - 1);
        pdl_launch(k_q, dim3(64), dim3(256), Wa_w);
        pdl_launch(k_attn, dim3(Bn), dim3(1024),
                   e_all, Wa_b, Va_w, Va_b, cross, t);
        pdl_launch(k_gigh, dim3(192), dim3(256), W_hh);
    }
    pdl_launch(k_gates, dim3(32), dim3(256),
               b_ih, b_hh, (const float*)g_h_ptr, hT,
               Wo_w, Wo_b, d_outputs, Tn - 1);
}